// round 5
// baseline (speedup 1.0000x reference)
#include <cuda_runtime.h>

// ---------------------------------------------------------------------------
// MultiHeadSelfAttention, fp32 baseline:
//   1) qkv = x @ qkv_w^T + qkv_b            (4096 x 3072, K=1024)
//   2) flash attention per (b, h, q-tile)   (T=2048, Dh=64, H=16, B=2)
//   3) out = ctx @ out_w^T + out_b          (4096 x 1024, K=1024)
// Scratch via __device__ globals (no allocation anywhere).
// ---------------------------------------------------------------------------

#define D_EMBED 1024
#define N_HEADS 16
#define D_HEAD  64
#define N_B     2
#define N_T     2048
#define M_TOT   (N_B * N_T)      // 4096
#define N_QKV   (3 * D_EMBED)    // 3072

__device__ float g_qkv[(size_t)M_TOT * N_QKV];   // 48 MB
__device__ float g_ctx[(size_t)M_TOT * D_EMBED]; // 16 MB

// ---------------------------------------------------------------------------
// SGEMM: C[m][n] = sum_k A[m][k] * W[n][k] + bias[n]
// Block tile 128x128, K-tile 8, 256 threads, 8x8 per thread (split 4+4).
// ---------------------------------------------------------------------------
__device__ __forceinline__ void gemm_body(
    const float* __restrict__ A, const float* __restrict__ W,
    const float* __restrict__ bias, float* __restrict__ C,
    int N, int K)
{
    __shared__ float As[8][128];
    __shared__ float Bs[8][128];

    const int t  = threadIdx.x;
    const int tx = t & 15;       // 0..15 (n micro-tile)
    const int ty = t >> 4;       // 0..15 (m micro-tile)
    const int m0 = blockIdx.y * 128;
    const int n0 = blockIdx.x * 128;

    // global loaders: each thread brings one float4 of A and one of W per K-tile
    const int lr = t >> 1;         // tile row 0..127
    const int lc = (t & 1) * 4;    // k offset 0 or 4
    const float* Ag = A + (size_t)(m0 + lr) * K + lc;
    const float* Wg = W + (size_t)(n0 + lr) * K + lc;

    float acc[8][8];
    #pragma unroll
    for (int i = 0; i < 8; i++)
        #pragma unroll
        for (int j = 0; j < 8; j++) acc[i][j] = 0.f;

    for (int k0 = 0; k0 < K; k0 += 8) {
        float4 av = *(const float4*)(Ag + k0);
        float4 wv = *(const float4*)(Wg + k0);
        __syncthreads();
        As[lc + 0][lr] = av.x; As[lc + 1][lr] = av.y;
        As[lc + 2][lr] = av.z; As[lc + 3][lr] = av.w;
        Bs[lc + 0][lr] = wv.x; Bs[lc + 1][lr] = wv.y;
        Bs[lc + 2][lr] = wv.z; Bs[lc + 3][lr] = wv.w;
        __syncthreads();

        #pragma unroll
        for (int k = 0; k < 8; k++) {
            float4 a0 = *(const float4*)&As[k][ty * 4];
            float4 a1 = *(const float4*)&As[k][64 + ty * 4];
            float4 b0 = *(const float4*)&Bs[k][tx * 4];
            float4 b1 = *(const float4*)&Bs[k][64 + tx * 4];
            float ar[8] = {a0.x, a0.y, a0.z, a0.w, a1.x, a1.y, a1.z, a1.w};
            float br[8] = {b0.x, b0.y, b0.z, b0.w, b1.x, b1.y, b1.z, b1.w};
            #pragma unroll
            for (int i = 0; i < 8; i++)
                #pragma unroll
                for (int j = 0; j < 8; j++)
                    acc[i][j] = fmaf(ar[i], br[j], acc[i][j]);
        }
    }

    float bv[8];
    #pragma unroll
    for (int j = 0; j < 4; j++) {
        bv[j]     = bias[n0 + tx * 4 + j];
        bv[4 + j] = bias[n0 + 64 + tx * 4 + j];
    }

    #pragma unroll
    for (int i = 0; i < 8; i++) {
        int row = m0 + ((i < 4) ? (ty * 4 + i) : (64 + ty * 4 + (i - 4)));
        float* cr = C + (size_t)row * N + n0;
        float4 v0 = make_float4(acc[i][0] + bv[0], acc[i][1] + bv[1],
                                acc[i][2] + bv[2], acc[i][3] + bv[3]);
        float4 v1 = make_float4(acc[i][4] + bv[4], acc[i][5] + bv[5],
                                acc[i][6] + bv[6], acc[i][7] + bv[7]);
        *(float4*)(cr + tx * 4)      = v0;
        *(float4*)(cr + 64 + tx * 4) = v1;
    }
}

__global__ __launch_bounds__(256, 2)
void qkv_gemm_kernel(const float* __restrict__ x,
                     const float* __restrict__ w,
                     const float* __restrict__ b)
{
    gemm_body(x, w, b, g_qkv, N_QKV, D_EMBED);
}

__global__ __launch_bounds__(256, 2)
void out_gemm_kernel(const float* __restrict__ w,
                     const float* __restrict__ b,
                     float* __restrict__ out)
{
    gemm_body(g_ctx, w, b, out, D_EMBED, D_EMBED);
}

// ---------------------------------------------------------------------------
// Flash attention: CTA = (b, h, 64-row Q tile), 256 threads = 64 rows x 4 lanes.
// K-tiles of 64. smem rows padded to 68 floats (PAD % 8 == 4) so both the
// strided S-phase K reads and the interleaved PV-phase V reads are
// bank-conflict-free. K buffer is reused as P buffer.
// ---------------------------------------------------------------------------
#define FPAD 68
#define FLASH_SMEM (3 * 64 * FPAD * (int)sizeof(float))  // 52224 B

__global__ __launch_bounds__(256)
void flash_kernel()
{
    extern __shared__ float sm[];
    float* Qs = sm;                 // [64][FPAD]
    float* KP = sm + 64 * FPAD;     // [64][FPAD]  K tile, then reused for P
    float* Vs = sm + 2 * 64 * FPAD; // [64][FPAD]

    const int b  = blockIdx.z;
    const int h  = blockIdx.y;
    const int q0 = blockIdx.x * 64;
    const int t  = threadIdx.x;
    const int r  = t >> 2;          // row 0..63
    const int l4 = t & 3;           // lane within row
    const int cb = l4 * 16;         // contiguous 16-col block for tile loads
    const float scale = 0.125f;     // 1/sqrt(64)

    // load Q tile (scaled)
    {
        const float* qg = g_qkv + (size_t)(b * N_T + q0 + r) * N_QKV
                        + h * D_HEAD + cb;
        #pragma unroll
        for (int u = 0; u < 16; u += 4) {
            float4 v = *(const float4*)(qg + u);
            *(float4*)&Qs[r * FPAD + cb + u] =
                make_float4(v.x * scale, v.y * scale, v.z * scale, v.w * scale);
        }
    }

    float mi = -1e30f, li = 0.f;
    float o[16];
    #pragma unroll
    for (int u = 0; u < 16; u++) o[u] = 0.f;

    for (int kt = 0; kt < N_T / 64; kt++) {
        __syncthreads();  // prior PV reads done (and Q visible on kt==0)
        {
            const float* kg = g_qkv + (size_t)(b * N_T + kt * 64 + r) * N_QKV
                            + D_EMBED + h * D_HEAD + cb;
            #pragma unroll
            for (int u = 0; u < 16; u += 4) {
                *(float4*)&KP[r * FPAD + cb + u] = *(const float4*)(kg + u);
                *(float4*)&Vs[r * FPAD + cb + u] = *(const float4*)(kg + D_EMBED + u);
            }
        }
        __syncthreads();

        // S = Q K^T for this thread's 16 strided columns (c = l4 + 4j)
        float s[16];
        #pragma unroll
        for (int j = 0; j < 16; j++) s[j] = 0.f;
        #pragma unroll
        for (int d = 0; d < 64; d += 4) {
            float4 q = *(const float4*)&Qs[r * FPAD + d];
            #pragma unroll
            for (int j = 0; j < 16; j++) {
                float4 k4 = *(const float4*)&KP[(l4 + 4 * j) * FPAD + d];
                s[j] = fmaf(q.x, k4.x, s[j]);
                s[j] = fmaf(q.y, k4.y, s[j]);
                s[j] = fmaf(q.z, k4.z, s[j]);
                s[j] = fmaf(q.w, k4.w, s[j]);
            }
        }

        // online softmax (row split across 4 lanes)
        float mt = s[0];
        #pragma unroll
        for (int j = 1; j < 16; j++) mt = fmaxf(mt, s[j]);
        mt = fmaxf(mt, __shfl_xor_sync(0xffffffffu, mt, 1));
        mt = fmaxf(mt, __shfl_xor_sync(0xffffffffu, mt, 2));
        const float mnew  = fmaxf(mi, mt);
        const float alpha = __expf(mi - mnew);
        float ls = 0.f;
        #pragma unroll
        for (int j = 0; j < 16; j++) { s[j] = __expf(s[j] - mnew); ls += s[j]; }
        ls += __shfl_xor_sync(0xffffffffu, ls, 1);
        ls += __shfl_xor_sync(0xffffffffu, ls, 2);
        li = li * alpha + ls;
        mi = mnew;
        #pragma unroll
        for (int u = 0; u < 16; u++) o[u] *= alpha;

        __syncthreads();  // everyone done reading K from KP
        #pragma unroll
        for (int j = 0; j < 16; j++) KP[r * FPAD + l4 + 4 * j] = s[j];
        __syncthreads();  // P visible

        // O += P @ V  (this thread owns cols {16w + l4*4 + i})
        #pragma unroll 2
        for (int c = 0; c < 64; c += 4) {
            float4 p4 = *(const float4*)&KP[r * FPAD + c];
            float pr[4] = {p4.x, p4.y, p4.z, p4.w};
            #pragma unroll
            for (int cc = 0; cc < 4; cc++) {
                float p = pr[cc];
                #pragma unroll
                for (int w = 0; w < 4; w++) {
                    float4 v4 = *(const float4*)&Vs[(c + cc) * FPAD + w * 16 + l4 * 4];
                    o[w * 4 + 0] = fmaf(p, v4.x, o[w * 4 + 0]);
                    o[w * 4 + 1] = fmaf(p, v4.y, o[w * 4 + 1]);
                    o[w * 4 + 2] = fmaf(p, v4.z, o[w * 4 + 2]);
                    o[w * 4 + 3] = fmaf(p, v4.w, o[w * 4 + 3]);
                }
            }
        }
    }

    const float inv = 1.f / li;
    float* og = g_ctx + (size_t)(b * N_T + q0 + r) * D_EMBED + h * D_HEAD;
    #pragma unroll
    for (int w = 0; w < 4; w++) {
        float4 v = make_float4(o[w * 4 + 0] * inv, o[w * 4 + 1] * inv,
                               o[w * 4 + 2] * inv, o[w * 4 + 3] * inv);
        *(float4*)(og + w * 16 + l4 * 4) = v;
    }
}

// ---------------------------------------------------------------------------
extern "C" void kernel_launch(void* const* d_in, const int* in_sizes, int n_in,
                              void* d_out, int out_size)
{
    (void)in_sizes; (void)n_in; (void)out_size;
    const float* x     = (const float*)d_in[0];
    const float* qkv_w = (const float*)d_in[1];
    const float* qkv_b = (const float*)d_in[2];
    const float* out_w = (const float*)d_in[3];
    const float* out_b = (const float*)d_in[4];
    float* out = (float*)d_out;

    qkv_gemm_kernel<<<dim3(N_QKV / 128, M_TOT / 128), 256>>>(x, qkv_w, qkv_b);

    cudaFuncSetAttribute(flash_kernel,
                         cudaFuncAttributeMaxDynamicSharedMemorySize,
                         FLASH_SMEM);
    flash_kernel<<<dim3(N_T / 64, N_HEADS, N_B), 256, FLASH_SMEM>>>();

    out_gemm_kernel<<<dim3(D_EMBED / 128, M_TOT / 128), 256>>>(out_w, out_b, out);
}

// round 6
// speedup vs baseline: 1.0721x; 1.0721x over previous
#include <cuda_runtime.h>

// ---------------------------------------------------------------------------
// MultiHeadSelfAttention fp32:
//   1) qkv = x @ qkv_w^T + qkv_b        (4096 x 3072, K=1024)  [double-buffered]
//   2) flash attention                  (register-tiled, 128x64 tiles)
//   3) out = ctx @ out_w^T + out_b      (4096 x 1024, K=1024)  [double-buffered]
// ---------------------------------------------------------------------------

#define D_EMBED 1024
#define N_HEADS 16
#define D_HEAD  64
#define N_B     2
#define N_T     2048
#define M_TOT   (N_B * N_T)      // 4096
#define N_QKV   (3 * D_EMBED)    // 3072

__device__ float g_qkv[(size_t)M_TOT * N_QKV];   // 48 MB
__device__ float g_ctx[(size_t)M_TOT * D_EMBED]; // 16 MB

// ---------------------------------------------------------------------------
// SGEMM: C[m][n] = sum_k A[m][k] * W[n][k] + bias[n]
// 128x128 tile, K-tile 8, 256 threads, 8x8/thread, double-buffered smem.
// ---------------------------------------------------------------------------
__device__ __forceinline__ void gemm_compute8(
    const float (*As)[128], const float (*Bs)[128],
    int tx, int ty, float acc[8][8])
{
    #pragma unroll
    for (int k = 0; k < 8; k++) {
        float4 a0 = *(const float4*)&As[k][ty * 4];
        float4 a1 = *(const float4*)&As[k][64 + ty * 4];
        float4 b0 = *(const float4*)&Bs[k][tx * 4];
        float4 b1 = *(const float4*)&Bs[k][64 + tx * 4];
        float ar[8] = {a0.x, a0.y, a0.z, a0.w, a1.x, a1.y, a1.z, a1.w};
        float br[8] = {b0.x, b0.y, b0.z, b0.w, b1.x, b1.y, b1.z, b1.w};
        #pragma unroll
        for (int i = 0; i < 8; i++)
            #pragma unroll
            for (int j = 0; j < 8; j++)
                acc[i][j] = fmaf(ar[i], br[j], acc[i][j]);
    }
}

__device__ __forceinline__ void gemm_body(
    const float* __restrict__ A, const float* __restrict__ W,
    const float* __restrict__ bias, float* __restrict__ C,
    int N, int K)
{
    __shared__ float As[2][8][128];
    __shared__ float Bs[2][8][128];

    const int t  = threadIdx.x;
    const int tx = t & 15;
    const int ty = t >> 4;
    const int m0 = blockIdx.y * 128;
    const int n0 = blockIdx.x * 128;

    const int lr = t >> 1;         // tile row 0..127
    const int lc = (t & 1) * 4;    // k offset 0 or 4
    const float* Ag = A + (size_t)(m0 + lr) * K + lc;
    const float* Wg = W + (size_t)(n0 + lr) * K + lc;

    float acc[8][8];
    #pragma unroll
    for (int i = 0; i < 8; i++)
        #pragma unroll
        for (int j = 0; j < 8; j++) acc[i][j] = 0.f;

    // prologue: fill buffer 0
    {
        float4 av = *(const float4*)(Ag);
        float4 wv = *(const float4*)(Wg);
        As[0][lc + 0][lr] = av.x; As[0][lc + 1][lr] = av.y;
        As[0][lc + 2][lr] = av.z; As[0][lc + 3][lr] = av.w;
        Bs[0][lc + 0][lr] = wv.x; Bs[0][lc + 1][lr] = wv.y;
        Bs[0][lc + 2][lr] = wv.z; Bs[0][lc + 3][lr] = wv.w;
    }
    __syncthreads();

    int cur = 0;
    for (int k0 = 8; k0 < K; k0 += 8) {
        float4 av = *(const float4*)(Ag + k0);
        float4 wv = *(const float4*)(Wg + k0);

        gemm_compute8(As[cur], Bs[cur], tx, ty, acc);

        const int nxt = cur ^ 1;
        As[nxt][lc + 0][lr] = av.x; As[nxt][lc + 1][lr] = av.y;
        As[nxt][lc + 2][lr] = av.z; As[nxt][lc + 3][lr] = av.w;
        Bs[nxt][lc + 0][lr] = wv.x; Bs[nxt][lc + 1][lr] = wv.y;
        Bs[nxt][lc + 2][lr] = wv.z; Bs[nxt][lc + 3][lr] = wv.w;
        __syncthreads();
        cur = nxt;
    }
    gemm_compute8(As[cur], Bs[cur], tx, ty, acc);

    float bv[8];
    #pragma unroll
    for (int j = 0; j < 4; j++) {
        bv[j]     = bias[n0 + tx * 4 + j];
        bv[4 + j] = bias[n0 + 64 + tx * 4 + j];
    }

    #pragma unroll
    for (int i = 0; i < 8; i++) {
        int row = m0 + ((i < 4) ? (ty * 4 + i) : (64 + ty * 4 + (i - 4)));
        float* cr = C + (size_t)row * N + n0;
        float4 v0 = make_float4(acc[i][0] + bv[0], acc[i][1] + bv[1],
                                acc[i][2] + bv[2], acc[i][3] + bv[3]);
        float4 v1 = make_float4(acc[i][4] + bv[4], acc[i][5] + bv[5],
                                acc[i][6] + bv[6], acc[i][7] + bv[7]);
        *(float4*)(cr + tx * 4)      = v0;
        *(float4*)(cr + 64 + tx * 4) = v1;
    }
}

__global__ __launch_bounds__(256, 2)
void qkv_gemm_kernel(const float* __restrict__ x,
                     const float* __restrict__ w,
                     const float* __restrict__ b)
{
    gemm_body(x, w, b, g_qkv, N_QKV, D_EMBED);
}

__global__ __launch_bounds__(256, 2)
void out_gemm_kernel(const float* __restrict__ w,
                     const float* __restrict__ b,
                     float* __restrict__ out)
{
    gemm_body(g_ctx, w, b, out, D_EMBED, D_EMBED);
}

// ---------------------------------------------------------------------------
// Flash attention v2: CTA = (b, h, 128-row Q tile), 256 threads.
// S tile 128x64, thread tile 8 rows x 4 cols (ty = t>>4 rows, tx = t&15 cols).
// Q/K/P stored d-major (transposed) with XOR-8 swizzle m(d)=((d>>4)&3)<<3 for
// conflict-free transposed stores and fragment loads. V natural layout.
// ---------------------------------------------------------------------------
#define QTILE  128
#define KTILE  64
#define QPITCH 132
#define KPITCH 68
#define FLASH_SMEM ((2 * KTILE * QPITCH + 2 * KTILE * KPITCH) * (int)sizeof(float)) // 102400

__global__ __launch_bounds__(256, 2)
void flash_kernel()
{
    extern __shared__ float sm[];
    float* Qs = sm;                         // [64][QPITCH]  Q^T  (d-major)
    float* Pt = sm + KTILE * QPITCH;        // [64][QPITCH]  P^T  (c-major)
    float* Ks = sm + 2 * KTILE * QPITCH;    // [64][KPITCH]  K^T  (d-major)
    float* Vs = Ks + KTILE * KPITCH;        // [64][KPITCH]  V    (k-major)

    const int b  = blockIdx.z;
    const int h  = blockIdx.y;
    const int q0 = blockIdx.x * QTILE;
    const int t  = threadIdx.x;
    const int tx = t & 15;
    const int ty = t >> 4;
    const int r0 = ty * 8;        // my 8 S/O rows
    const int c0 = tx * 4;        // my 4 S cols / 4 O dcols
    const float scale = 0.125f;   // 1/sqrt(64)

    // ---- load Q tile (128 x 64) transposed into Qs[d][r^m], scaled ----
    {
        const int qr = t >> 1;            // 0..127
        const int dh = (t & 1) * 32;      // 0 or 32
        const float* qg = g_qkv + (size_t)(b * N_T + q0 + qr) * N_QKV
                        + h * D_HEAD + dh;
        #pragma unroll
        for (int u = 0; u < 8; u++) {
            float4 v = *(const float4*)(qg + u * 4);
            const int d = dh + u * 4;
            const int rr = qr ^ (((d >> 4) & 3) << 3);
            Qs[(d + 0) * QPITCH + rr] = v.x * scale;
            Qs[(d + 1) * QPITCH + rr] = v.y * scale;
            Qs[(d + 2) * QPITCH + rr] = v.z * scale;
            Qs[(d + 3) * QPITCH + rr] = v.w * scale;
        }
    }

    float mi[8], li[8], o[8][4];
    #pragma unroll
    for (int i = 0; i < 8; i++) {
        mi[i] = -1e30f; li[i] = 0.f;
        #pragma unroll
        for (int j = 0; j < 4; j++) o[i][j] = 0.f;
    }

    for (int kt = 0; kt < N_T / KTILE; kt++) {
        __syncthreads();  // prev tile's S (Ks) + PV (Vs, Pt) reads done; Q ready on kt==0

        // ---- load K (transposed+swizzled) and V (natural) tiles ----
        {
            const int kr = t >> 2;            // key 0..63
            const int dh = (t & 3) * 16;
            const float* kg = g_qkv + (size_t)(b * N_T + kt * KTILE + kr) * N_QKV
                            + D_EMBED + h * D_HEAD + dh;
            const float* vg = kg + D_EMBED;
            #pragma unroll
            for (int u = 0; u < 4; u++) {
                float4 kv = *(const float4*)(kg + u * 4);
                const int d = dh + u * 4;
                const int cc = kr ^ (((d >> 4) & 3) << 3);
                Ks[(d + 0) * KPITCH + cc] = kv.x;
                Ks[(d + 1) * KPITCH + cc] = kv.y;
                Ks[(d + 2) * KPITCH + cc] = kv.z;
                Ks[(d + 3) * KPITCH + cc] = kv.w;
                *(float4*)&Vs[kr * KPITCH + d] = *(const float4*)(vg + u * 4);
            }
        }
        __syncthreads();

        // ---- S = Q K^T : 8x4 per thread ----
        float s[8][4];
        #pragma unroll
        for (int i = 0; i < 8; i++)
            #pragma unroll
            for (int j = 0; j < 4; j++) s[i][j] = 0.f;

        #pragma unroll
        for (int dq = 0; dq < 4; dq++) {
            const int m  = dq << 3;
            const int ra = r0 ^ m;
            const int ca = c0 ^ m;
            #pragma unroll 4
            for (int dd = 0; dd < 16; dd++) {
                const int d = dq * 16 + dd;
                float4 qa = *(const float4*)&Qs[d * QPITCH + ra];
                float4 qb = *(const float4*)&Qs[d * QPITCH + ra + 4];
                float4 kk = *(const float4*)&Ks[d * KPITCH + ca];
                float qr8[8] = {qa.x, qa.y, qa.z, qa.w, qb.x, qb.y, qb.z, qb.w};
                float kc4[4] = {kk.x, kk.y, kk.z, kk.w};
                #pragma unroll
                for (int i = 0; i < 8; i++)
                    #pragma unroll
                    for (int j = 0; j < 4; j++)
                        s[i][j] = fmaf(qr8[i], kc4[j], s[i][j]);
            }
        }

        // ---- online softmax (row stats reduced over the 16 tx lanes) ----
        #pragma unroll
        for (int i = 0; i < 8; i++) {
            float mt = fmaxf(fmaxf(s[i][0], s[i][1]), fmaxf(s[i][2], s[i][3]));
            mt = fmaxf(mt, __shfl_xor_sync(0xffffffffu, mt, 1));
            mt = fmaxf(mt, __shfl_xor_sync(0xffffffffu, mt, 2));
            mt = fmaxf(mt, __shfl_xor_sync(0xffffffffu, mt, 4));
            mt = fmaxf(mt, __shfl_xor_sync(0xffffffffu, mt, 8));
            const float mnew = fmaxf(mi[i], mt);
            const float al   = __expf(mi[i] - mnew);
            float ls = 0.f;
            #pragma unroll
            for (int j = 0; j < 4; j++) {
                s[i][j] = __expf(s[i][j] - mnew);
                ls += s[i][j];
            }
            ls += __shfl_xor_sync(0xffffffffu, ls, 1);
            ls += __shfl_xor_sync(0xffffffffu, ls, 2);
            ls += __shfl_xor_sync(0xffffffffu, ls, 4);
            ls += __shfl_xor_sync(0xffffffffu, ls, 8);
            li[i] = li[i] * al + ls;
            mi[i] = mnew;
            #pragma unroll
            for (int j = 0; j < 4; j++) o[i][j] *= al;
        }

        // ---- write P^T (c-major, swizzled rows); Pt disjoint from Ks ----
        {
            const int m = ((tx >> 2) & 3) << 3;   // same for c0..c0+3
            const int ra = r0 ^ m;
            #pragma unroll
            for (int j = 0; j < 4; j++) {
                const int c = c0 + j;
                *(float4*)&Pt[c * QPITCH + ra] =
                    make_float4(s[0][j], s[1][j], s[2][j], s[3][j]);
                *(float4*)&Pt[c * QPITCH + ra + 4] =
                    make_float4(s[4][j], s[5][j], s[6][j], s[7][j]);
            }
        }
        __syncthreads();

        // ---- O += P V : 8x4 per thread ----
        #pragma unroll
        for (int kq = 0; kq < 4; kq++) {
            const int m  = kq << 3;
            const int ra = r0 ^ m;
            #pragma unroll 4
            for (int kk2 = 0; kk2 < 16; kk2++) {
                const int k = kq * 16 + kk2;
                float4 pa = *(const float4*)&Pt[k * QPITCH + ra];
                float4 pb = *(const float4*)&Pt[k * QPITCH + ra + 4];
                float4 vv = *(const float4*)&Vs[k * KPITCH + c0];
                float pr8[8] = {pa.x, pa.y, pa.z, pa.w, pb.x, pb.y, pb.z, pb.w};
                float vc4[4] = {vv.x, vv.y, vv.z, vv.w};
                #pragma unroll
                for (int i = 0; i < 8; i++)
                    #pragma unroll
                    for (int j = 0; j < 4; j++)
                        o[i][j] = fmaf(pr8[i], vc4[j], o[i][j]);
            }
        }
    }

    // ---- epilogue ----
    #pragma unroll
    for (int i = 0; i < 8; i++) {
        const float inv = 1.f / li[i];
        float* og = g_ctx + (size_t)(b * N_T + q0 + r0 + i) * D_EMBED
                  + h * D_HEAD + c0;
        *(float4*)og = make_float4(o[i][0] * inv, o[i][1] * inv,
                                   o[i][2] * inv, o[i][3] * inv);
    }
}

// ---------------------------------------------------------------------------
extern "C" void kernel_launch(void* const* d_in, const int* in_sizes, int n_in,
                              void* d_out, int out_size)
{
    (void)in_sizes; (void)n_in; (void)out_size;
    const float* x     = (const float*)d_in[0];
    const float* qkv_w = (const float*)d_in[1];
    const float* qkv_b = (const float*)d_in[2];
    const float* out_w = (const float*)d_in[3];
    const float* out_b = (const float*)d_in[4];
    float* out = (float*)d_out;

    qkv_gemm_kernel<<<dim3(N_QKV / 128, M_TOT / 128), 256>>>(x, qkv_w, qkv_b);

    cudaFuncSetAttribute(flash_kernel,
                         cudaFuncAttributeMaxDynamicSharedMemorySize,
                         FLASH_SMEM);
    flash_kernel<<<dim3(N_T / QTILE, N_HEADS, N_B), 256, FLASH_SMEM>>>();

    out_gemm_kernel<<<dim3(D_EMBED / 128, M_TOT / 128), 256>>>(out_w, out_b, out);
}

// round 8
// speedup vs baseline: 1.7923x; 1.6717x over previous
#include <cuda_runtime.h>
#include <cstdint>

// ---------------------------------------------------------------------------
// MultiHeadSelfAttention:
//   1) qkv = x @ qkv_w^T + qkv_b    mma.sync tf32-split-x3 (fp32-accurate)
//   2) flash attention (fp32, register-tiled)  -> g_ctx
//   3) out = ctx @ out_w^T + out_b  mma.sync tf32-split-x3
// ---------------------------------------------------------------------------

#define D_EMBED 1024
#define N_HEADS 16
#define D_HEAD  64
#define N_B     2
#define N_T     2048
#define M_TOT   (N_B * N_T)      // 4096
#define N_QKV   (3 * D_EMBED)    // 3072
#define K_DIM   1024

__device__ float g_qkv[(size_t)M_TOT * N_QKV];   // 48 MB
__device__ float g_ctx[(size_t)M_TOT * D_EMBED]; // 16 MB

// ---------------------------------------------------------------------------
// tf32 helpers (sm_80-era PTX, valid on plain sm_103 target)
// ---------------------------------------------------------------------------
__device__ __forceinline__ uint32_t f2tf(float x) {
    uint32_t r;
    asm("cvt.rna.tf32.f32 %0, %1;" : "=r"(r) : "f"(x));
    return r;
}

__device__ __forceinline__ void cvt_split(float x, uint32_t& hi, uint32_t& lo) {
    hi = f2tf(x);
    lo = f2tf(x - __uint_as_float(hi));
}

__device__ __forceinline__ void mma_tf32(float* d, const uint32_t* a,
                                         const uint32_t* b) {
    asm volatile(
        "mma.sync.aligned.m16n8k8.row.col.f32.tf32.tf32.f32 "
        "{%0,%1,%2,%3}, {%4,%5,%6,%7}, {%8,%9}, {%0,%1,%2,%3};"
        : "+f"(d[0]), "+f"(d[1]), "+f"(d[2]), "+f"(d[3])
        : "r"(a[0]), "r"(a[1]), "r"(a[2]), "r"(a[3]), "r"(b[0]), "r"(b[1]));
}

// ---------------------------------------------------------------------------
// GEMM: C[m][n] = sum_k A[m][k] * W[n][k] + bias[n]
// CTA 128x128, warps 2(M)x4(N) -> warp tile 64x32, K-tile 16 (2 k8 steps),
// double-buffered smem (pitch 20 => conflict-free fragment loads),
// tf32 split-x3 mma.sync. A row-major fragments; W rows are the col-major B.
// ---------------------------------------------------------------------------
#define TKK 16
#define PIT 20

__device__ __forceinline__ void mma_gemm_body(
    const float* __restrict__ A, const float* __restrict__ W,
    const float* __restrict__ bias, float* __restrict__ C, int N)
{
    __shared__ float As[2][128][PIT];
    __shared__ float Ws[2][128][PIT];

    const int t    = threadIdx.x;
    const int lane = t & 31;
    const int w    = t >> 5;
    const int wm   = w & 1;        // 0..1  (M)
    const int wn   = w >> 1;       // 0..3  (N)
    const int g    = lane >> 2;    // 0..7
    const int tg   = lane & 3;     // 0..3
    const int m0   = blockIdx.y * 128;
    const int n0   = blockIdx.x * 128;

    const int lr = t >> 1;          // 0..127
    const int lk = (t & 1) * 8;     // 0 or 8
    const float* Ag = A + (size_t)(m0 + lr) * K_DIM + lk;
    const float* Wg = W + (size_t)(n0 + lr) * K_DIM + lk;

    float acc[4][4][4];
    #pragma unroll
    for (int i = 0; i < 4; i++)
        #pragma unroll
        for (int j = 0; j < 4; j++)
            #pragma unroll
            for (int e = 0; e < 4; e++) acc[i][j][e] = 0.f;

    // prologue: tile 0
    {
        float4 a0 = *(const float4*)(Ag);
        float4 a1 = *(const float4*)(Ag + 4);
        float4 w0 = *(const float4*)(Wg);
        float4 w1 = *(const float4*)(Wg + 4);
        *(float4*)&As[0][lr][lk]     = a0;
        *(float4*)&As[0][lr][lk + 4] = a1;
        *(float4*)&Ws[0][lr][lk]     = w0;
        *(float4*)&Ws[0][lr][lk + 4] = w1;
    }
    __syncthreads();

    int cur = 0;
    for (int kt = 0; kt < K_DIM / TKK; kt++) {
        const bool more = (kt + 1 < K_DIM / TKK);
        float4 pa0, pa1, pw0, pw1;
        if (more) {
            const float* Ap = Ag + (kt + 1) * TKK;
            const float* Wp = Wg + (kt + 1) * TKK;
            pa0 = *(const float4*)(Ap);
            pa1 = *(const float4*)(Ap + 4);
            pw0 = *(const float4*)(Wp);
            pw1 = *(const float4*)(Wp + 4);
        }

        #pragma unroll
        for (int s = 0; s < 2; s++) {
            const int ks = s * 8;
            uint32_t Ah[4][4], Al[4][4], Bh[4][2], Bl[4][2];
            #pragma unroll
            for (int mf = 0; mf < 4; mf++) {
                const int rb = wm * 64 + mf * 16;
                cvt_split(As[cur][rb + g][ks + tg],         Ah[mf][0], Al[mf][0]);
                cvt_split(As[cur][rb + g + 8][ks + tg],     Ah[mf][1], Al[mf][1]);
                cvt_split(As[cur][rb + g][ks + tg + 4],     Ah[mf][2], Al[mf][2]);
                cvt_split(As[cur][rb + g + 8][ks + tg + 4], Ah[mf][3], Al[mf][3]);
            }
            #pragma unroll
            for (int nf = 0; nf < 4; nf++) {
                const int nb = wn * 32 + nf * 8;
                cvt_split(Ws[cur][nb + g][ks + tg],     Bh[nf][0], Bl[nf][0]);
                cvt_split(Ws[cur][nb + g][ks + tg + 4], Bh[nf][1], Bl[nf][1]);
            }
            #pragma unroll
            for (int mf = 0; mf < 4; mf++)
                #pragma unroll
                for (int nf = 0; nf < 4; nf++) {
                    mma_tf32(acc[mf][nf], Ah[mf], Bh[nf]);
                    mma_tf32(acc[mf][nf], Ah[mf], Bl[nf]);
                    mma_tf32(acc[mf][nf], Al[mf], Bh[nf]);
                }
        }

        if (more) {
            const int nxt = cur ^ 1;
            *(float4*)&As[nxt][lr][lk]     = pa0;
            *(float4*)&As[nxt][lr][lk + 4] = pa1;
            *(float4*)&Ws[nxt][lr][lk]     = pw0;
            *(float4*)&Ws[nxt][lr][lk + 4] = pw1;
            __syncthreads();
            cur = nxt;
        }
    }

    // epilogue: d0,d1 -> row g, cols 2tg,2tg+1 ; d2,d3 -> row g+8
    #pragma unroll
    for (int mf = 0; mf < 4; mf++) {
        const int r = m0 + wm * 64 + mf * 16 + g;
        #pragma unroll
        for (int nf = 0; nf < 4; nf++) {
            const int c = n0 + wn * 32 + nf * 8 + 2 * tg;
            const float b0 = bias[c], b1 = bias[c + 1];
            float2 v0 = make_float2(acc[mf][nf][0] + b0, acc[mf][nf][1] + b1);
            float2 v1 = make_float2(acc[mf][nf][2] + b0, acc[mf][nf][3] + b1);
            *(float2*)(C + (size_t)r * N + c)       = v0;
            *(float2*)(C + (size_t)(r + 8) * N + c) = v1;
        }
    }
}

__global__ __launch_bounds__(256, 1)
void gemm_qkv_kernel(const float* __restrict__ x,
                     const float* __restrict__ w,
                     const float* __restrict__ b)
{
    mma_gemm_body(x, w, b, g_qkv, N_QKV);
}

__global__ __launch_bounds__(256, 1)
void gemm_out_kernel(const float* __restrict__ w,
                     const float* __restrict__ b,
                     float* __restrict__ out)
{
    mma_gemm_body(g_ctx, w, b, out, D_EMBED);
}

// ---------------------------------------------------------------------------
// Flash attention (fp32, proven): CTA = (b, h, 128-row Q tile), 256 threads,
// 8x4 register tile, XOR-8 swizzled transposed Q/K/P in smem.
// ---------------------------------------------------------------------------
#define QTILE  128
#define KTILE  64
#define QPITCH 132
#define KPITCH 68
#define FLASH_SMEM ((2 * KTILE * QPITCH + 2 * KTILE * KPITCH) * (int)sizeof(float))

__global__ __launch_bounds__(256, 2)
void flash_kernel()
{
    extern __shared__ float fsm[];
    float* Qs = fsm;
    float* Pt = fsm + KTILE * QPITCH;
    float* Ks = fsm + 2 * KTILE * QPITCH;
    float* Vs = Ks + KTILE * KPITCH;

    const int b  = blockIdx.z;
    const int h  = blockIdx.y;
    const int q0 = blockIdx.x * QTILE;
    const int t  = threadIdx.x;
    const int tx = t & 15;
    const int ty = t >> 4;
    const int r0 = ty * 8;
    const int c0 = tx * 4;
    const float scale = 0.125f;

    {
        const int qr = t >> 1;
        const int dh = (t & 1) * 32;
        const float* qg = g_qkv + (size_t)(b * N_T + q0 + qr) * N_QKV
                        + h * D_HEAD + dh;
        #pragma unroll
        for (int u = 0; u < 8; u++) {
            float4 v = *(const float4*)(qg + u * 4);
            const int d = dh + u * 4;
            const int rr = qr ^ (((d >> 4) & 3) << 3);
            Qs[(d + 0) * QPITCH + rr] = v.x * scale;
            Qs[(d + 1) * QPITCH + rr] = v.y * scale;
            Qs[(d + 2) * QPITCH + rr] = v.z * scale;
            Qs[(d + 3) * QPITCH + rr] = v.w * scale;
        }
    }

    float mi[8], li[8], o[8][4];
    #pragma unroll
    for (int i = 0; i < 8; i++) {
        mi[i] = -1e30f; li[i] = 0.f;
        #pragma unroll
        for (int j = 0; j < 4; j++) o[i][j] = 0.f;
    }

    for (int kt = 0; kt < N_T / KTILE; kt++) {
        __syncthreads();
        {
            const int kr = t >> 2;
            const int dh = (t & 3) * 16;
            const float* kg = g_qkv + (size_t)(b * N_T + kt * KTILE + kr) * N_QKV
                            + D_EMBED + h * D_HEAD + dh;
            const float* vg = kg + D_EMBED;
            #pragma unroll
            for (int u = 0; u < 4; u++) {
                float4 kv = *(const float4*)(kg + u * 4);
                const int d = dh + u * 4;
                const int cc = kr ^ (((d >> 4) & 3) << 3);
                Ks[(d + 0) * KPITCH + cc] = kv.x;
                Ks[(d + 1) * KPITCH + cc] = kv.y;
                Ks[(d + 2) * KPITCH + cc] = kv.z;
                Ks[(d + 3) * KPITCH + cc] = kv.w;
                *(float4*)&Vs[kr * KPITCH + d] = *(const float4*)(vg + u * 4);
            }
        }
        __syncthreads();

        float s[8][4];
        #pragma unroll
        for (int i = 0; i < 8; i++)
            #pragma unroll
            for (int j = 0; j < 4; j++) s[i][j] = 0.f;

        #pragma unroll
        for (int dq = 0; dq < 4; dq++) {
            const int m  = dq << 3;
            const int ra = r0 ^ m;
            const int ca = c0 ^ m;
            #pragma unroll 4
            for (int dd = 0; dd < 16; dd++) {
                const int d = dq * 16 + dd;
                float4 qa = *(const float4*)&Qs[d * QPITCH + ra];
                float4 qb = *(const float4*)&Qs[d * QPITCH + ra + 4];
                float4 kk = *(const float4*)&Ks[d * KPITCH + ca];
                float qr8[8] = {qa.x, qa.y, qa.z, qa.w, qb.x, qb.y, qb.z, qb.w};
                float kc4[4] = {kk.x, kk.y, kk.z, kk.w};
                #pragma unroll
                for (int i = 0; i < 8; i++)
                    #pragma unroll
                    for (int j = 0; j < 4; j++)
                        s[i][j] = fmaf(qr8[i], kc4[j], s[i][j]);
            }
        }

        #pragma unroll
        for (int i = 0; i < 8; i++) {
            float mt = fmaxf(fmaxf(s[i][0], s[i][1]), fmaxf(s[i][2], s[i][3]));
            mt = fmaxf(mt, __shfl_xor_sync(0xffffffffu, mt, 1));
            mt = fmaxf(mt, __shfl_xor_sync(0xffffffffu, mt, 2));
            mt = fmaxf(mt, __shfl_xor_sync(0xffffffffu, mt, 4));
            mt = fmaxf(mt, __shfl_xor_sync(0xffffffffu, mt, 8));
            const float mnew = fmaxf(mi[i], mt);
            const float al   = __expf(mi[i] - mnew);
            float ls = 0.f;
            #pragma unroll
            for (int j = 0; j < 4; j++) {
                s[i][j] = __expf(s[i][j] - mnew);
                ls += s[i][j];
            }
            ls += __shfl_xor_sync(0xffffffffu, ls, 1);
            ls += __shfl_xor_sync(0xffffffffu, ls, 2);
            ls += __shfl_xor_sync(0xffffffffu, ls, 4);
            ls += __shfl_xor_sync(0xffffffffu, ls, 8);
            li[i] = li[i] * al + ls;
            mi[i] = mnew;
            #pragma unroll
            for (int j = 0; j < 4; j++) o[i][j] *= al;
        }

        {
            const int m = ((tx >> 2) & 3) << 3;
            const int ra = r0 ^ m;
            #pragma unroll
            for (int j = 0; j < 4; j++) {
                const int c = c0 + j;
                *(float4*)&Pt[c * QPITCH + ra] =
                    make_float4(s[0][j], s[1][j], s[2][j], s[3][j]);
                *(float4*)&Pt[c * QPITCH + ra + 4] =
                    make_float4(s[4][j], s[5][j], s[6][j], s[7][j]);
            }
        }
        __syncthreads();

        #pragma unroll
        for (int kq = 0; kq < 4; kq++) {
            const int m  = kq << 3;
            const int ra = r0 ^ m;
            #pragma unroll 4
            for (int kk2 = 0; kk2 < 16; kk2++) {
                const int k = kq * 16 + kk2;
                float4 pa = *(const float4*)&Pt[k * QPITCH + ra];
                float4 pb = *(const float4*)&Pt[k * QPITCH + ra + 4];
                float4 vv = *(const float4*)&Vs[k * KPITCH + c0];
                float pr8[8] = {pa.x, pa.y, pa.z, pa.w, pb.x, pb.y, pb.z, pb.w};
                float vc4[4] = {vv.x, vv.y, vv.z, vv.w};
                #pragma unroll
                for (int i = 0; i < 8; i++)
                    #pragma unroll
                    for (int j = 0; j < 4; j++)
                        o[i][j] = fmaf(pr8[i], vc4[j], o[i][j]);
            }
        }
    }

    #pragma unroll
    for (int i = 0; i < 8; i++) {
        const float inv = 1.f / li[i];
        float* og = g_ctx + (size_t)(b * N_T + q0 + r0 + i) * D_EMBED
                  + h * D_HEAD + c0;
        *(float4*)og = make_float4(o[i][0] * inv, o[i][1] * inv,
                                   o[i][2] * inv, o[i][3] * inv);
    }
}

// ---------------------------------------------------------------------------
extern "C" void kernel_launch(void* const* d_in, const int* in_sizes, int n_in,
                              void* d_out, int out_size)
{
    (void)in_sizes; (void)n_in; (void)out_size;
    const float* x     = (const float*)d_in[0];
    const float* qkv_w = (const float*)d_in[1];
    const float* qkv_b = (const float*)d_in[2];
    const float* out_w = (const float*)d_in[3];
    const float* out_b = (const float*)d_in[4];
    float* out = (float*)d_out;

    gemm_qkv_kernel<<<dim3(N_QKV / 128, M_TOT / 128), 256>>>(x, qkv_w, qkv_b);

    cudaFuncSetAttribute(flash_kernel,
                         cudaFuncAttributeMaxDynamicSharedMemorySize, FLASH_SMEM);
    flash_kernel<<<dim3(N_T / QTILE, N_HEADS, N_B), 256, FLASH_SMEM>>>();

    gemm_out_kernel<<<dim3(D_EMBED / 128, M_TOT / 128), 256>>>(out_w, out_b, out);
}